// round 12
// baseline (speedup 1.0000x reference)
#include <cuda_runtime.h>
#include <math.h>

// Problem constants (fixed-shape problem)
#define NTOK  8192
#define DDIM  1024
#define EEXP  64
#define RRANK 64
#define GGRP  8
#define MLOC  8

#define TILE_T 64           // tokens per expert tile
#define MAX_TILES 512       // per slot: <= N/TILE_T + E = 192

// ---------------- scratch (device globals; no allocations) ----------------
__device__ int   g_eid[NTOK * 2];      // global expert id per (token, slot)
__device__ float g_gate2[NTOK * 2];    // gate per (token, slot)
__device__ int   g_cnt[2][EEXP];
__device__ int   g_off[2][EEXP];
__device__ int   g_fill[2][EEXP];
__device__ int   g_tok[2][NTOK];       // token index, grouped by expert, per slot
__device__ float g_tg[2][NTOK];        // matching gate
__device__ int   g_tiles[2][MAX_TILES];// packed: (e<<16) | tile_index_within_expert
__device__ int   g_ntiles[2];
__device__ float g_extra[NTOK * DDIM]; // slot-1 partial output (merged by add_kernel)

// ---------------- init: zero counters ----------------
__global__ void init_kernel() {
    int t = threadIdx.x;
    if (t < EEXP) {
        g_cnt[0][t] = 0; g_cnt[1][t] = 0;
        g_fill[0][t] = 0; g_fill[1][t] = 0;
    }
    if (t == 0) { g_ntiles[0] = 0; g_ntiles[1] = 0; }
}

// ---------------- routing: one warp per token (unchanged, verified) ----------------
__global__ void routing_kernel(const float* __restrict__ h,
                               const float* __restrict__ Wg,
                               const float* __restrict__ bg,
                               const float* __restrict__ Wloc,
                               float* __restrict__ o_eid,    // may be null
                               float* __restrict__ o_gate,   // may be null
                               float* __restrict__ o_grp,    // may be null
                               int n)
{
    int warp = (blockIdx.x * blockDim.x + threadIdx.x) >> 5;
    int lane = threadIdx.x & 31;
    if (warp >= n) return;

    const float* hrow = h + (size_t)warp * DDIM;

    float hv[32];
#pragma unroll
    for (int i = 0; i < 32; i++) hv[i] = hrow[i * 32 + lane];

    // ---- stage 1: group scores (G=8) ----
    float sg[GGRP];
#pragma unroll
    for (int g = 0; g < GGRP; g++) sg[g] = 0.f;
#pragma unroll
    for (int i = 0; i < 32; i++) {
        int d = i * 32 + lane;
        const float4* wp = (const float4*)(Wg + (size_t)d * GGRP);
        float4 wa = wp[0], wb = wp[1];
        float x = hv[i];
        sg[0] += x * wa.x; sg[1] += x * wa.y; sg[2] += x * wa.z; sg[3] += x * wa.w;
        sg[4] += x * wb.x; sg[5] += x * wb.y; sg[6] += x * wb.z; sg[7] += x * wb.w;
    }
#pragma unroll
    for (int g = 0; g < GGRP; g++) {
#pragma unroll
        for (int off = 16; off > 0; off >>= 1)
            sg[g] += __shfl_xor_sync(0xFFFFFFFFu, sg[g], off);
        sg[g] += bg[g];
    }
    int gi = 0; float best = sg[0];
#pragma unroll
    for (int g = 1; g < GGRP; g++) if (sg[g] > best) { best = sg[g]; gi = g; }

    // ---- stage 2: local scores for selected group (M=8) ----
    float sl[MLOC];
#pragma unroll
    for (int m = 0; m < MLOC; m++) sl[m] = 0.f;
    const float* wl = Wloc + (size_t)gi * DDIM * MLOC;
#pragma unroll
    for (int i = 0; i < 32; i++) {
        int d = i * 32 + lane;
        const float4* wp = (const float4*)(wl + (size_t)d * MLOC);
        float4 wa = wp[0], wb = wp[1];
        float x = hv[i];
        sl[0] += x * wa.x; sl[1] += x * wa.y; sl[2] += x * wa.z; sl[3] += x * wa.w;
        sl[4] += x * wb.x; sl[5] += x * wb.y; sl[6] += x * wb.z; sl[7] += x * wb.w;
    }
#pragma unroll
    for (int m = 0; m < MLOC; m++) {
#pragma unroll
        for (int off = 16; off > 0; off >>= 1)
            sl[m] += __shfl_xor_sync(0xFFFFFFFFu, sl[m], off);
    }
    int m1 = 0; float v1 = sl[0];
#pragma unroll
    for (int m = 1; m < MLOC; m++) if (sl[m] > v1) { v1 = sl[m]; m1 = m; }
    int m2 = -1; float v2 = -INFINITY;
#pragma unroll
    for (int m = 0; m < MLOC; m++) if (m != m1 && sl[m] > v2) { v2 = sl[m]; m2 = m; }

    float e2 = expf(v2 - v1);
    float inv = 1.0f / (1.0f + e2);
    float gate0 = inv;
    float gate1 = e2 * inv;

    int eid0 = gi * MLOC + m1;
    int eid1 = gi * MLOC + m2;

    if (lane == 0) {
        g_eid[2 * warp + 0] = eid0;
        g_eid[2 * warp + 1] = eid1;
        g_gate2[2 * warp + 0] = gate0;
        g_gate2[2 * warp + 1] = gate1;
        atomicAdd(&g_cnt[0][eid0], 1);
        atomicAdd(&g_cnt[1][eid1], 1);
        if (o_eid)  { o_eid[2 * warp + 0] = (float)eid0; o_eid[2 * warp + 1] = (float)eid1; }
        if (o_gate) { o_gate[2 * warp + 0] = gate0;      o_gate[2 * warp + 1] = gate1; }
        if (o_grp)  { o_grp[warp] = (float)gi; }
    }
}

// ---------------- prefix sums + tile lists (tiny; single thread) ----------------
__global__ void prefix_kernel() {
    if (threadIdx.x != 0 || blockIdx.x != 0) return;
#pragma unroll
    for (int s = 0; s < 2; s++) {
        int acc = 0, nt = 0;
        for (int e = 0; e < EEXP; e++) {
            g_off[s][e] = acc;
            int c = g_cnt[s][e];
            acc += c;
            int t = (c + TILE_T - 1) / TILE_T;
            for (int i = 0; i < t && nt < MAX_TILES; i++)
                g_tiles[s][nt++] = (e << 16) | i;
        }
        g_ntiles[s] = nt;
    }
}

// ---------------- scatter tokens into per-expert, per-slot buckets ----------------
__global__ void scatter_kernel(int n) {
    int t = blockIdx.x * blockDim.x + threadIdx.x;
    if (t >= n) return;
#pragma unroll
    for (int j = 0; j < 2; j++) {
        int e = g_eid[2 * t + j];
        int p = g_off[j][e] + atomicAdd(&g_fill[j][e], 1);
        g_tok[j][p] = t;
        g_tg[j][p]  = g_gate2[2 * t + j];
    }
}

// ---------------- expert compute: one tile = (slot, expert, 64 tokens) ----------------
// Both slots in ONE launch (slot0 -> out, slot1 -> g_extra); no atomics.
// Phase 1: A = gate * relu(H @ W1[e])  (64 x 64), ping-pong k-chunks of 32, reg-prefetch.
// Phase 2: O = A @ W2[e]               (64 x 1024), 64-col tiles, reg-prefetch.
// Thread map: tq = tid&15 -> tokens {4tq..4tq+3}; rg = tid>>4 -> 4 cols {4rg..4rg+3}.
// 16 outputs/thread -> 16 FFMA per 2 LDS.128 in both inner loops.
__global__ void __launch_bounds__(256)
expert_kernel(const float* __restrict__ h,
              const float* __restrict__ W1,
              const float* __restrict__ W2,
              float* __restrict__ out)
{
    // s_u aliases: phase1 H^T ping-pong [2][32][68] (4352 floats)
    //              phase2 A^T           [64][68]    (4352 floats)
    __shared__ __align__(16) float s_u[4352];
    // s_w aliases: phase1 W1 ping-pong 2 x (32x64); phase2 W2 single 64x64 (4096 floats)
    __shared__ __align__(16) float s_w[4096];
    __shared__ int   tok_s[TILE_T];
    __shared__ float gsc[TILE_T];

#define HT(b, k, t) s_u[(b) * 2176 + (k) * 68 + (t)]
#define AT(r, t)    s_u[(r) * 68 + (t)]

    int tid = threadIdx.x;
    int tq = tid & 15;            // token group: tokens 4tq..4tq+3
    int rg = tid >> 4;            // col group:   cols   4rg..4rg+3 (0..15)
    int tq4 = 4 * tq, rg4 = 4 * rg;

    // fill maps
    int fh_k = tid & 31;          // k within 32-chunk
    int fh_t = tid >> 5;          // +8*i -> token (0..63)
    int fw_c = tid & 63;          // col within 64
    int fw_r = tid >> 6;          // +4*i -> row

    int nt0 = g_ntiles[0];
    int ntt = nt0 + g_ntiles[1];

    for (int tile = blockIdx.x; tile < ntt; tile += gridDim.x) {
        int slot = (tile >= nt0) ? 1 : 0;
        int tloc = slot ? tile - nt0 : tile;
        int desc = g_tiles[slot][tloc];
        int e  = desc >> 16;
        int ti = desc & 0xFFFF;
        int cnt_e = g_cnt[slot][e];
        int base  = g_off[slot][e] + ti * TILE_T;
        int nv = cnt_e - ti * TILE_T;
        if (nv > TILE_T) nv = TILE_T;

        if (tid < TILE_T) {
            int rr = tid < nv ? tid : (nv - 1);   // clamp; invalid rows masked at store
            tok_s[tid] = g_tok[slot][base + rr];
            gsc[tid]   = g_tg[slot][base + rr];
        }
        __syncthreads();

        const float* W1e = W1 + (size_t)e * DDIM * RRANK;

        // byte-row offsets for this thread's 8 H-fill tokens (fh_t + 8i)
        int hoff[8];
#pragma unroll
        for (int i = 0; i < 8; i++) hoff[i] = tok_s[fh_t + 8 * i] * DDIM;

        float hr[8], wr[8];
        // preload k-chunk 0
#pragma unroll
        for (int i = 0; i < 8; i++) hr[i] = h[(size_t)hoff[i] + fh_k];
#pragma unroll
        for (int i = 0; i < 8; i++) wr[i] = W1e[(size_t)(fw_r + 4 * i) * RRANK + fw_c];
#pragma unroll
        for (int i = 0; i < 8; i++) HT(0, fh_k, fh_t + 8 * i) = hr[i];
#pragma unroll
        for (int i = 0; i < 8; i++) s_w[(fw_r + 4 * i) * 64 + fw_c] = wr[i];
        __syncthreads();

        // ---------------- phase 1 ----------------
        float acc[4][4];
#pragma unroll
        for (int t = 0; t < 4; t++)
#pragma unroll
            for (int c = 0; c < 4; c++) acc[t][c] = 0.f;

        for (int kt = 0; kt < DDIM / 32; kt++) {
            int b = kt & 1;
            if (kt < DDIM / 32 - 1) {
                int k0 = (kt + 1) * 32;
#pragma unroll
                for (int i = 0; i < 8; i++) hr[i] = h[(size_t)hoff[i] + k0 + fh_k];
#pragma unroll
                for (int i = 0; i < 8; i++)
                    wr[i] = W1e[(size_t)(k0 + fw_r + 4 * i) * RRANK + fw_c];
            }
            const float* wb = s_w + b * 2048;
#pragma unroll
            for (int kk = 0; kk < 32; kk++) {
                float4 hv = *(const float4*)&HT(b, kk, tq4);
                float4 wv = *(const float4*)&wb[kk * 64 + rg4];
                acc[0][0] += hv.x * wv.x; acc[0][1] += hv.x * wv.y; acc[0][2] += hv.x * wv.z; acc[0][3] += hv.x * wv.w;
                acc[1][0] += hv.y * wv.x; acc[1][1] += hv.y * wv.y; acc[1][2] += hv.y * wv.z; acc[1][3] += hv.y * wv.w;
                acc[2][0] += hv.z * wv.x; acc[2][1] += hv.z * wv.y; acc[2][2] += hv.z * wv.z; acc[2][3] += hv.z * wv.w;
                acc[3][0] += hv.w * wv.x; acc[3][1] += hv.w * wv.y; acc[3][2] += hv.w * wv.z; acc[3][3] += hv.w * wv.w;
            }
            if (kt < DDIM / 32 - 1) {
                int nb = 1 - b;
#pragma unroll
                for (int i = 0; i < 8; i++) HT(nb, fh_k, fh_t + 8 * i) = hr[i];
#pragma unroll
                for (int i = 0; i < 8; i++) s_w[nb * 2048 + (fw_r + 4 * i) * 64 + fw_c] = wr[i];
            }
            __syncthreads();
        }

        // ---------------- A^T write (aliases H^T region) + W2 tile-0 prefetch ----------------
        const float* W2e = W2 + (size_t)e * RRANK * DDIM;
        float wr2[16];
#pragma unroll
        for (int i = 0; i < 16; i++)
            wr2[i] = W2e[(size_t)(fw_r + 4 * i) * DDIM + fw_c];

        {
            float g0 = gsc[tq4 + 0], g1 = gsc[tq4 + 1], g2 = gsc[tq4 + 2], g3 = gsc[tq4 + 3];
#pragma unroll
            for (int c = 0; c < 4; c++) {
                float4 a;
                a.x = fmaxf(acc[0][c], 0.f) * g0;
                a.y = fmaxf(acc[1][c], 0.f) * g1;
                a.z = fmaxf(acc[2][c], 0.f) * g2;
                a.w = fmaxf(acc[3][c], 0.f) * g3;
                *(float4*)&AT(rg4 + c, tq4) = a;
            }
        }
#pragma unroll
        for (int i = 0; i < 16; i++)
            s_w[(fw_r + 4 * i) * 64 + fw_c] = wr2[i];
        __syncthreads();   // A^T + W2 tile 0 visible

        // ---------------- phase 2 ----------------
        float* dst = slot ? g_extra : out;
        bool v[4];
        size_t ob[4];
#pragma unroll
        for (int t = 0; t < 4; t++) {
            v[t]  = (tq4 + t < nv);
            ob[t] = (size_t)tok_s[tq4 + t] * DDIM;
        }

        for (int ct = 0; ct < 16; ct++) {
            if (ct < 15) {
                int c0 = (ct + 1) * 64;
#pragma unroll
                for (int i = 0; i < 16; i++)
                    wr2[i] = W2e[(size_t)(fw_r + 4 * i) * DDIM + c0 + fw_c];
            }
            float o[4][4];
#pragma unroll
            for (int t = 0; t < 4; t++)
#pragma unroll
                for (int c = 0; c < 4; c++) o[t][c] = 0.f;
#pragma unroll
            for (int r = 0; r < RRANK; r++) {
                float4 av = *(const float4*)&AT(r, tq4);
                float4 wv = *(const float4*)&s_w[r * 64 + rg4];
                o[0][0] += av.x * wv.x; o[0][1] += av.x * wv.y; o[0][2] += av.x * wv.z; o[0][3] += av.x * wv.w;
                o[1][0] += av.y * wv.x; o[1][1] += av.y * wv.y; o[1][2] += av.y * wv.z; o[1][3] += av.y * wv.w;
                o[2][0] += av.z * wv.x; o[2][1] += av.z * wv.y; o[2][2] += av.z * wv.z; o[2][3] += av.z * wv.w;
                o[3][0] += av.w * wv.x; o[3][1] += av.w * wv.y; o[3][2] += av.w * wv.z; o[3][3] += av.w * wv.w;
            }
            int c = ct * 64 + rg4;
#pragma unroll
            for (int t = 0; t < 4; t++)
                if (v[t]) *(float4*)&dst[ob[t] + c] = make_float4(o[t][0], o[t][1], o[t][2], o[t][3]);
            __syncthreads();            // all reads of s_w done (last iter: also A^T/tok_s)
            if (ct < 15) {
#pragma unroll
                for (int i = 0; i < 16; i++)
                    s_w[(fw_r + 4 * i) * 64 + fw_c] = wr2[i];
                __syncthreads();
            }
        }
    }
#undef HT
#undef AT
}

// ---------------- merge: out += g_extra ----------------
__global__ void add_kernel(float* __restrict__ out, int n4) {
    int i = blockIdx.x * blockDim.x + threadIdx.x;
    int stride = gridDim.x * blockDim.x;
    const float4* ex = (const float4*)g_extra;
    float4* o = (float4*)out;
    for (; i < n4; i += stride) {
        float4 a = o[i], b = ex[i];
        a.x += b.x; a.y += b.y; a.z += b.z; a.w += b.w;
        o[i] = a;
    }
}

// ---------------- launch ----------------
extern "C" void kernel_launch(void* const* d_in, const int* in_sizes, int n_in,
                              void* d_out, int out_size)
{
    const float* h    = (const float*)d_in[0];
    const float* Wg   = (const float*)d_in[1];
    const float* bg   = (const float*)d_in[2];
    const float* Wloc = (const float*)d_in[3];
    const float* W1   = (const float*)d_in[4];
    const float* W2   = (const float*)d_in[5];

    int n = in_sizes[0] / DDIM;                 // 8192
    if (n > NTOK) n = NTOK;

    float* out = (float*)d_out;

    // Optional concatenated tail outputs: out(N*D), expert_ids(2N), gate(2N), group_idx(N)
    size_t need = (size_t)n * DDIM + 5 * (size_t)n;
    float* o_eid  = nullptr;
    float* o_gate = nullptr;
    float* o_grp  = nullptr;
    if ((size_t)out_size >= need) {
        o_eid  = out + (size_t)n * DDIM;
        o_gate = o_eid + 2 * (size_t)n;
        o_grp  = o_gate + 2 * (size_t)n;
    }

    init_kernel<<<1, 128>>>();
    routing_kernel<<<(n + 7) / 8, 256>>>(h, Wg, bg, Wloc, o_eid, o_gate, o_grp, n);
    prefix_kernel<<<1, 32>>>();
    scatter_kernel<<<(n + 255) / 256, 256>>>(n);
    // Both slots in one wave: slot0 tiles write `out`, slot1 tiles write g_extra
    expert_kernel<<<384, 256>>>(h, W1, W2, out);
    // out += g_extra
    add_kernel<<<1024, 256>>>(out, n * DDIM / 4);
}